// round 10
// baseline (speedup 1.0000x reference)
#include <cuda_runtime.h>

#define N_NODES 50000
#define F1 32
#define F2 16
#define EPT 4          // edges per thread in edge-pass kernels
#define T 256          // threads per block
#define MAXE 4500000   // capacity of sorted edge array (actual = 4.2M)

// ---------------- scratch (device globals; no allocation allowed) ----------
__device__ int   g_cnt_out[3][N_NODES];                  // out-degree counts
__device__ int   g_cnt_in [3][N_NODES];                  // in-degree counts
__device__ int   g_off[3][N_NODES];                      // CSR segment start (absolute)
__device__ int   g_cur[3][N_NODES];                      // scatter cursors
__device__ int   g_esrc[MAXE];                           // src ids sorted by (r, dst)
__device__ __align__(16) float g_h1[3][N_NODES * F2];    // per-relation pre-agg messages
__device__ __align__(16) float g_m [3][N_NODES * F2];    // per-relation raw aggregates
__device__ float g_s   [3][N_NODES];                     // layer-2 scalar projections
__device__ float g_out3[3][N_NODES];                     // layer-2 raw accumulators

__device__ __forceinline__ float rinv_of(int c) {
    return rsqrtf(fmaxf((float)c, 1.0f));
}

// Map fused blockIdx -> (relation, local block)
struct RelSel { const int* s; const int* d; int E; int r; int b; };
__device__ __forceinline__ RelSel pick_rel(
    int b, const int* s0, const int* d0, int E0, int B0,
    const int* s1, const int* d1, int E1, int B1,
    const int* s2, const int* d2, int E2) {
    RelSel rs;
    if (b < B0)            { rs = {s0, d0, E0, 0, b}; }
    else if (b < B0 + B1)  { rs = {s1, d1, E1, 1, b - B0}; }
    else                   { rs = {s2, d2, E2, 2, b - B0 - B1}; }
    return rs;
}

// ---------------- K1: zero degree counters ---------------------------------
__global__ void k_zero() {
    int i = blockIdx.x * blockDim.x + threadIdx.x;
    const int nd = 3 * N_NODES;
    if (i < nd) {
        ((int*)g_cnt_out)[i] = 0;
        ((int*)g_cnt_in)[i]  = 0;
    }
}

// ---------------- K2: fused degree counting (all relations) ----------------
__global__ void k_count_all(const int* __restrict__ s0, const int* __restrict__ d0, int E0, int B0,
                            const int* __restrict__ s1, const int* __restrict__ d1, int E1, int B1,
                            const int* __restrict__ s2, const int* __restrict__ d2, int E2) {
    RelSel rs = pick_rel(blockIdx.x, s0, d0, E0, B0, s1, d1, E1, B1, s2, d2, E2);
    int i0 = (rs.b * T + threadIdx.x) * EPT;
    int* co = &g_cnt_out[rs.r][0];
    int* ci = &g_cnt_in [rs.r][0];
    if (i0 + EPT <= rs.E) {
        int4 sv = *(const int4*)(rs.s + i0);
        int4 dv = *(const int4*)(rs.d + i0);
        atomicAdd(co + sv.x, 1); atomicAdd(co + sv.y, 1);
        atomicAdd(co + sv.z, 1); atomicAdd(co + sv.w, 1);
        atomicAdd(ci + dv.x, 1); atomicAdd(ci + dv.y, 1);
        atomicAdd(ci + dv.z, 1); atomicAdd(ci + dv.w, 1);
    } else {
        for (int i = i0; i < rs.E; i++) {
            atomicAdd(co + rs.s[i], 1);
            atomicAdd(ci + rs.d[i], 1);
        }
    }
}

// ---------------- K3: per-relation exclusive scan of in-degrees ------------
// grid = 3 (one block per relation), block = 1024
__global__ void k_scan(int base0, int base1, int base2) {
    const int BT = 1024;
    __shared__ int sm[BT];
    int r = blockIdx.x;
    int base = (r == 0) ? base0 : (r == 1) ? base1 : base2;
    const int CH = (N_NODES + BT - 1) / BT;
    int t = threadIdx.x;
    int lo = t * CH;
    int hi = min(lo + CH, N_NODES);

    int sum = 0;
    for (int i = lo; i < hi; i++) sum += g_cnt_in[r][i];
    sm[t] = sum;
    __syncthreads();
    // Hillis-Steele inclusive scan
    for (int off = 1; off < BT; off <<= 1) {
        int y = (t >= off) ? sm[t - off] : 0;
        __syncthreads();
        sm[t] += y;
        __syncthreads();
    }
    int run = base + sm[t] - sum;   // exclusive prefix
    for (int i = lo; i < hi; i++) {
        g_off[r][i] = run;
        g_cur[r][i] = run;
        run += g_cnt_in[r][i];
    }
}

// ---------------- K4: scatter edges into CSR (sorted by dst) ---------------
__global__ void k_scatter_all(const int* __restrict__ s0, const int* __restrict__ d0, int E0, int B0,
                              const int* __restrict__ s1, const int* __restrict__ d1, int E1, int B1,
                              const int* __restrict__ s2, const int* __restrict__ d2, int E2) {
    RelSel rs = pick_rel(blockIdx.x, s0, d0, E0, B0, s1, d1, E1, B1, s2, d2, E2);
    int i0 = (rs.b * T + threadIdx.x) * EPT;
    int* cur = &g_cur[rs.r][0];
    if (i0 + EPT <= rs.E) {
        int4 sv = *(const int4*)(rs.s + i0);
        int4 dv = *(const int4*)(rs.d + i0);
        int p0 = atomicAdd(cur + dv.x, 1);
        int p1 = atomicAdd(cur + dv.y, 1);
        int p2 = atomicAdd(cur + dv.z, 1);
        int p3 = atomicAdd(cur + dv.w, 1);
        g_esrc[p0] = sv.x; g_esrc[p1] = sv.y;
        g_esrc[p2] = sv.z; g_esrc[p3] = sv.w;
    } else {
        for (int i = i0; i < rs.E; i++) {
            int p = atomicAdd(cur + rs.d[i], 1);
            g_esrc[p] = rs.s[i];
        }
    }
}

// ---------------- K5: h1_r[n] = (x[n] * rinv_out_r[n]) @ W1[r] -------------
__global__ void k_h1(const float* __restrict__ x, const float* __restrict__ W1) {
    __shared__ float sW[3 * F1 * F2];
    for (int t = threadIdx.x; t < 3 * F1 * F2; t += blockDim.x) sW[t] = W1[t];
    __syncthreads();
    int n = blockIdx.x * blockDim.x + threadIdx.x;
    if (n >= N_NODES) return;

    float xr[F1];
    const float4* xp = (const float4*)(x + (size_t)n * F1);
#pragma unroll
    for (int k = 0; k < F1 / 4; k++) {
        float4 v = xp[k];
        xr[4 * k + 0] = v.x; xr[4 * k + 1] = v.y;
        xr[4 * k + 2] = v.z; xr[4 * k + 3] = v.w;
    }
#pragma unroll
    for (int r = 0; r < 3; r++) {
        float scale = rinv_of(g_cnt_out[r][n]);
        float acc[F2];
#pragma unroll
        for (int j = 0; j < F2; j++) acc[j] = 0.0f;
        const float* wr = sW + r * F1 * F2;
#pragma unroll
        for (int i = 0; i < F1; i++) {
            float xv = xr[i];
#pragma unroll
            for (int j = 0; j < F2; j++) acc[j] = fmaf(xv, wr[i * F2 + j], acc[j]);
        }
        float4* op = (float4*)&g_h1[r][(size_t)n * F2];
#pragma unroll
        for (int k = 0; k < F2 / 4; k++) {
            float4 v;
            v.x = acc[4 * k + 0] * scale; v.y = acc[4 * k + 1] * scale;
            v.z = acc[4 * k + 2] * scale; v.w = acc[4 * k + 3] * scale;
            op[k] = v;
        }
    }
}

// ---------------- K6: atomic-free layer-1 gather ---------------------------
// thread = (r, dst, chunk): 3*N*4 threads; chunk = one float4 of the 16-wide row.
__global__ void k_gather1() {
    int tid = blockIdx.x * blockDim.x + threadIdx.x;
    int chunk = tid & 3;
    int idx = tid >> 2;
    if (idx >= 3 * N_NODES) return;
    int r = idx / N_NODES;
    int n = idx - r * N_NODES;

    int start = g_off[r][n];
    int cnt   = g_cnt_in[r][n];
    const int* ep = g_esrc + start;
    const float4* h1 = (const float4*)&g_h1[r][0];

    float4 a0 = make_float4(0.f, 0.f, 0.f, 0.f);
    float4 a1 = make_float4(0.f, 0.f, 0.f, 0.f);
    int e = 0;
    for (; e + 2 <= cnt; e += 2) {
        int s0 = ep[e], s1 = ep[e + 1];
        float4 v0 = h1[(size_t)s0 * 4 + chunk];
        float4 v1 = h1[(size_t)s1 * 4 + chunk];
        a0.x += v0.x; a0.y += v0.y; a0.z += v0.z; a0.w += v0.w;
        a1.x += v1.x; a1.y += v1.y; a1.z += v1.z; a1.w += v1.w;
    }
    if (e < cnt) {
        int s0 = ep[e];
        float4 v0 = h1[(size_t)s0 * 4 + chunk];
        a0.x += v0.x; a0.y += v0.y; a0.z += v0.z; a0.w += v0.w;
    }
    a0.x += a1.x; a0.y += a1.y; a0.z += a1.z; a0.w += a1.w;
    ((float4*)&g_m[r][(size_t)n * F2])[chunk] = a0;
}

// ---------------- K7: finish layer 1, project layer 2 ----------------------
__global__ void k_l2prep(const float* __restrict__ b1, const float* __restrict__ W2) {
    __shared__ float sb1[F2];
    __shared__ float sW2[3][F2];
    if (threadIdx.x < F2)
        sb1[threadIdx.x] = b1[threadIdx.x] + b1[F2 + threadIdx.x] + b1[2 * F2 + threadIdx.x];
    if (threadIdx.x < 3 * F2)
        sW2[threadIdx.x / F2][threadIdx.x % F2] = W2[threadIdx.x];
    __syncthreads();

    int n = blockIdx.x * blockDim.x + threadIdx.x;
    if (n >= N_NODES) return;

    float h[F2];
#pragma unroll
    for (int j = 0; j < F2; j++) h[j] = sb1[j];
#pragma unroll
    for (int r = 0; r < 3; r++) {
        float ri = rinv_of(g_cnt_in[r][n]);
        const float4* mp = (const float4*)&g_m[r][(size_t)n * F2];
#pragma unroll
        for (int k = 0; k < F2 / 4; k++) {
            float4 v = mp[k];
            h[4 * k + 0] = fmaf(v.x, ri, h[4 * k + 0]);
            h[4 * k + 1] = fmaf(v.y, ri, h[4 * k + 1]);
            h[4 * k + 2] = fmaf(v.z, ri, h[4 * k + 2]);
            h[4 * k + 3] = fmaf(v.w, ri, h[4 * k + 3]);
        }
    }
#pragma unroll
    for (int j = 0; j < F2; j++) h[j] = fmaxf(h[j], 0.0f);

#pragma unroll
    for (int r = 0; r < 3; r++) {
        float dot = 0.0f;
#pragma unroll
        for (int j = 0; j < F2; j++) dot = fmaf(h[j], sW2[r][j], dot);
        g_s[r][n] = dot * rinv_of(g_cnt_out[r][n]);
    }
}

// ---------------- K8: atomic-free layer-2 gather ---------------------------
// thread = (r, dst): scalar gathers of g_s over the same CSR.
__global__ void k_gather2() {
    int idx = blockIdx.x * blockDim.x + threadIdx.x;
    if (idx >= 3 * N_NODES) return;
    int r = idx / N_NODES;
    int n = idx - r * N_NODES;

    int start = g_off[r][n];
    int cnt   = g_cnt_in[r][n];
    const int* ep = g_esrc + start;
    const float* sc = &g_s[r][0];

    float a = 0.0f, b = 0.0f;
    int e = 0;
    for (; e + 2 <= cnt; e += 2) {
        a += sc[ep[e]];
        b += sc[ep[e + 1]];
    }
    if (e < cnt) a += sc[ep[e]];
    g_out3[r][n] = a + b;
}

// ---------------- K9: final: scale + bias + store to d_out -----------------
__global__ void k_final(const float* __restrict__ b2, float* __restrict__ out) {
    __shared__ float sb2sum;
    if (threadIdx.x == 0) sb2sum = b2[0] + b2[1] + b2[2];
    __syncthreads();
    int n = blockIdx.x * blockDim.x + threadIdx.x;
    if (n >= N_NODES) return;
    float v = sb2sum;
#pragma unroll
    for (int r = 0; r < 3; r++)
        v = fmaf(g_out3[r][n], rinv_of(g_cnt_in[r][n]), v);
    out[n] = v;
}

// ---------------- launch ----------------------------------------------------
extern "C" void kernel_launch(void* const* d_in, const int* in_sizes, int n_in,
                              void* d_out, int out_size) {
    const float* x = (const float*)d_in[0];
    const int* s0 = (const int*)d_in[1]; const int* d0 = (const int*)d_in[2];
    const int* s1 = (const int*)d_in[3]; const int* d1 = (const int*)d_in[4];
    const int* s2 = (const int*)d_in[5]; const int* d2 = (const int*)d_in[6];
    int E0 = in_sizes[1], E1 = in_sizes[3], E2 = in_sizes[5];
    const float* W1 = (const float*)d_in[7];
    const float* b1 = (const float*)d_in[8];
    const float* W2 = (const float*)d_in[9];
    const float* b2 = (const float*)d_in[10];
    float* out = (float*)d_out;

    const int PER_BLK = T * EPT;
    int B0 = (E0 + PER_BLK - 1) / PER_BLK;
    int B1 = (E1 + PER_BLK - 1) / PER_BLK;
    int B2 = (E2 + PER_BLK - 1) / PER_BLK;
    int BE = B0 + B1 + B2;

    k_zero<<<(3 * N_NODES + T - 1) / T, T>>>();
    k_count_all<<<BE, T>>>(s0, d0, E0, B0, s1, d1, E1, B1, s2, d2, E2);
    k_scan<<<3, 1024>>>(0, E0, E0 + E1);
    k_scatter_all<<<BE, T>>>(s0, d0, E0, B0, s1, d1, E1, B1, s2, d2, E2);
    k_h1<<<(N_NODES + T - 1) / T, T>>>(x, W1);
    k_gather1<<<(3 * N_NODES * 4 + T - 1) / T, T>>>();
    k_l2prep<<<(N_NODES + T - 1) / T, T>>>(b1, W2);
    k_gather2<<<(3 * N_NODES + T - 1) / T, T>>>();
    k_final<<<(N_NODES + T - 1) / T, T>>>(b2, out);
}